// round 1
// baseline (speedup 1.0000x reference)
#include <cuda_runtime.h>
#include <math.h>
#include <stdint.h>

#define H_DIM 4096
#define I_DIM 11008
#define M_DIM 8192

// Scratch for intermediate h = silu(x@wg) * (x@wu)   [M, I] fp32
__device__ float g_h[(size_t)M_DIM * I_DIM];

// ---------------------------------------------------------------------------
// Kernel 1: fused gate/up GEMM + SiLU*mul epilogue
// C tile 128x64, BK=16, 256 threads, per-thread 8x4 for each of gate & up.
// x:  [M, 4096] row-major
// wg, wu: [4096, 11008] row-major
// ---------------------------------------------------------------------------
__global__ __launch_bounds__(256, 2)
void k_gateup(const float* __restrict__ x,
              const float* __restrict__ wg,
              const float* __restrict__ wu)
{
    const int K = H_DIM;
    const int N = I_DIM;
    const int BM = 128, BN = 64, BK = 16;

    // grouped rasterization: concurrent CTAs share 16 M-tiles (x stays in L2)
    const int num_pid_m = M_DIM / BM;       // 64
    const int num_pid_n = N / BN;           // 172
    const int GROUP_M = 16;
    int pid = blockIdx.x;
    int group_size = GROUP_M * num_pid_n;
    int group_id = pid / group_size;
    int first_pid_m = group_id * GROUP_M;
    int group_m = min(GROUP_M, num_pid_m - first_pid_m);
    int pid_m = first_pid_m + (pid % group_m);
    int pid_n = (pid % group_size) / group_m;

    const int m0 = pid_m * BM;
    const int n0 = pid_n * BN;

    __shared__ float As[2][BK][BM + 4];   // transposed x tile (padded)
    __shared__ float Bg[2][BK][BN];
    __shared__ float Bu[2][BK][BN];

    const int tid = threadIdx.x;
    const int tx = tid & 15;   // 0..15 -> 4 cols each
    const int ty = tid >> 4;   // 0..15 -> 8 rows each

    // global-load assignments
    const int arow = tid >> 2;   // 0..63 (and +64)
    const int ac4  = tid & 3;    // float4 index within 16-wide row
    const int brow = tid >> 4;   // 0..15
    const int bc4  = tid & 15;   // float4 index within 64-wide row

    const float* xrow0 = x + (long long)(m0 + arow) * K + ac4 * 4;
    const float* xrow1 = x + (long long)(m0 + arow + 64) * K + ac4 * 4;

    float4 pa0, pa1, pg4, pu4;

    float accg[8][4];
    float accu[8][4];
#pragma unroll
    for (int i = 0; i < 8; i++)
#pragma unroll
        for (int j = 0; j < 4; j++) { accg[i][j] = 0.f; accu[i][j] = 0.f; }

    const int KT = K / BK;   // 256

    // prologue: load tile 0
    {
        const long long k0 = 0;
        pa0 = *(const float4*)(xrow0 + k0);
        pa1 = *(const float4*)(xrow1 + k0);
        pg4 = *(const float4*)(wg + (k0 + brow) * (long long)N + n0 + bc4 * 4);
        pu4 = *(const float4*)(wu + (k0 + brow) * (long long)N + n0 + bc4 * 4);
        As[0][ac4 * 4 + 0][arow] = pa0.x;
        As[0][ac4 * 4 + 1][arow] = pa0.y;
        As[0][ac4 * 4 + 2][arow] = pa0.z;
        As[0][ac4 * 4 + 3][arow] = pa0.w;
        As[0][ac4 * 4 + 0][arow + 64] = pa1.x;
        As[0][ac4 * 4 + 1][arow + 64] = pa1.y;
        As[0][ac4 * 4 + 2][arow + 64] = pa1.z;
        As[0][ac4 * 4 + 3][arow + 64] = pa1.w;
        *(float4*)&Bg[0][brow][bc4 * 4] = pg4;
        *(float4*)&Bu[0][brow][bc4 * 4] = pu4;
    }
    __syncthreads();

    for (int kt = 0; kt < KT; ++kt) {
        const int cur = kt & 1;
        const int nxt = cur ^ 1;
        if (kt + 1 < KT) {
            const long long k0 = (long long)(kt + 1) * BK;
            pa0 = *(const float4*)(xrow0 + k0);
            pa1 = *(const float4*)(xrow1 + k0);
            pg4 = *(const float4*)(wg + (k0 + brow) * (long long)N + n0 + bc4 * 4);
            pu4 = *(const float4*)(wu + (k0 + brow) * (long long)N + n0 + bc4 * 4);
        }

#pragma unroll
        for (int kk = 0; kk < BK; ++kk) {
            float4 a0 = *(const float4*)&As[cur][kk][ty * 8];
            float4 a1 = *(const float4*)&As[cur][kk][ty * 8 + 4];
            float4 bg = *(const float4*)&Bg[cur][kk][tx * 4];
            float4 bu = *(const float4*)&Bu[cur][kk][tx * 4];
            float a[8] = {a0.x, a0.y, a0.z, a0.w, a1.x, a1.y, a1.z, a1.w};
            float g[4] = {bg.x, bg.y, bg.z, bg.w};
            float u[4] = {bu.x, bu.y, bu.z, bu.w};
#pragma unroll
            for (int i = 0; i < 8; i++) {
#pragma unroll
                for (int j = 0; j < 4; j++) {
                    accg[i][j] = fmaf(a[i], g[j], accg[i][j]);
                    accu[i][j] = fmaf(a[i], u[j], accu[i][j]);
                }
            }
        }

        if (kt + 1 < KT) {
            As[nxt][ac4 * 4 + 0][arow] = pa0.x;
            As[nxt][ac4 * 4 + 1][arow] = pa0.y;
            As[nxt][ac4 * 4 + 2][arow] = pa0.z;
            As[nxt][ac4 * 4 + 3][arow] = pa0.w;
            As[nxt][ac4 * 4 + 0][arow + 64] = pa1.x;
            As[nxt][ac4 * 4 + 1][arow + 64] = pa1.y;
            As[nxt][ac4 * 4 + 2][arow + 64] = pa1.z;
            As[nxt][ac4 * 4 + 3][arow + 64] = pa1.w;
            *(float4*)&Bg[nxt][brow][bc4 * 4] = pg4;
            *(float4*)&Bu[nxt][brow][bc4 * 4] = pu4;
        }
        __syncthreads();
    }

    // epilogue: h = silu(gate) * up
    float* hp = g_h + (long long)m0 * N + n0;
#pragma unroll
    for (int i = 0; i < 8; i++) {
        const int row = ty * 8 + i;
        float4 o;
        float gv, sv;
        gv = accg[i][0]; sv = gv / (1.f + expf(-gv)); o.x = sv * accu[i][0];
        gv = accg[i][1]; sv = gv / (1.f + expf(-gv)); o.y = sv * accu[i][1];
        gv = accg[i][2]; sv = gv / (1.f + expf(-gv)); o.z = sv * accu[i][2];
        gv = accg[i][3]; sv = gv / (1.f + expf(-gv)); o.w = sv * accu[i][3];
        *(float4*)(hp + (long long)row * N + tx * 4) = o;
    }
}

// ---------------------------------------------------------------------------
// Kernel 2: y = h @ w_down
// C tile 128x128, BK=16, 256 threads, 8x8 per thread.
// h: [M, 11008], wd: [11008, 4096], y: [M, 4096]
// ---------------------------------------------------------------------------
__global__ __launch_bounds__(256, 2)
void k_down(const float* __restrict__ wd,
            float* __restrict__ y)
{
    const int K = I_DIM;    // 11008
    const int N = H_DIM;    // 4096
    const int BM = 128, BN = 128, BK = 16;

    const int num_pid_m = M_DIM / BM;   // 64
    const int num_pid_n = N / BN;       // 32
    const int GROUP_M = 8;
    int pid = blockIdx.x;
    int group_size = GROUP_M * num_pid_n;
    int group_id = pid / group_size;
    int first_pid_m = group_id * GROUP_M;
    int group_m = min(GROUP_M, num_pid_m - first_pid_m);
    int pid_m = first_pid_m + (pid % group_m);
    int pid_n = (pid % group_size) / group_m;

    const int m0 = pid_m * BM;
    const int n0 = pid_n * BN;

    __shared__ float As[2][BK][BM + 4];
    __shared__ float Bs[2][BK][BN];

    const int tid = threadIdx.x;
    const int tx = tid & 15;   // 0..15 -> 8 cols each
    const int ty = tid >> 4;   // 0..15 -> 8 rows each

    const int arow = tid >> 2;   // 0..63 (and +64)
    const int ac4  = tid & 3;
    // B tile: 16 rows x 128 cols = 512 float4, 2 per thread
    const int br0 = tid >> 5;          // 0..7  (and +8)
    const int bc4 = tid & 31;          // 0..31

    const float* hrow0 = g_h + (long long)(m0 + arow) * K + ac4 * 4;
    const float* hrow1 = g_h + (long long)(m0 + arow + 64) * K + ac4 * 4;

    float4 pa0, pa1, pb0, pb1;

    float acc[8][8];
#pragma unroll
    for (int i = 0; i < 8; i++)
#pragma unroll
        for (int j = 0; j < 8; j++) acc[i][j] = 0.f;

    const int KT = K / BK;   // 688

    {
        const long long k0 = 0;
        pa0 = *(const float4*)(hrow0 + k0);
        pa1 = *(const float4*)(hrow1 + k0);
        pb0 = *(const float4*)(wd + (k0 + br0) * (long long)N + n0 + bc4 * 4);
        pb1 = *(const float4*)(wd + (k0 + br0 + 8) * (long long)N + n0 + bc4 * 4);
        As[0][ac4 * 4 + 0][arow] = pa0.x;
        As[0][ac4 * 4 + 1][arow] = pa0.y;
        As[0][ac4 * 4 + 2][arow] = pa0.z;
        As[0][ac4 * 4 + 3][arow] = pa0.w;
        As[0][ac4 * 4 + 0][arow + 64] = pa1.x;
        As[0][ac4 * 4 + 1][arow + 64] = pa1.y;
        As[0][ac4 * 4 + 2][arow + 64] = pa1.z;
        As[0][ac4 * 4 + 3][arow + 64] = pa1.w;
        *(float4*)&Bs[0][br0][bc4 * 4] = pb0;
        *(float4*)&Bs[0][br0 + 8][bc4 * 4] = pb1;
    }
    __syncthreads();

    for (int kt = 0; kt < KT; ++kt) {
        const int cur = kt & 1;
        const int nxt = cur ^ 1;
        if (kt + 1 < KT) {
            const long long k0 = (long long)(kt + 1) * BK;
            pa0 = *(const float4*)(hrow0 + k0);
            pa1 = *(const float4*)(hrow1 + k0);
            pb0 = *(const float4*)(wd + (k0 + br0) * (long long)N + n0 + bc4 * 4);
            pb1 = *(const float4*)(wd + (k0 + br0 + 8) * (long long)N + n0 + bc4 * 4);
        }

#pragma unroll
        for (int kk = 0; kk < BK; ++kk) {
            float4 a0 = *(const float4*)&As[cur][kk][ty * 8];
            float4 a1 = *(const float4*)&As[cur][kk][ty * 8 + 4];
            float4 b0 = *(const float4*)&Bs[cur][kk][tx * 8];
            float4 b1 = *(const float4*)&Bs[cur][kk][tx * 8 + 4];
            float a[8] = {a0.x, a0.y, a0.z, a0.w, a1.x, a1.y, a1.z, a1.w};
            float b[8] = {b0.x, b0.y, b0.z, b0.w, b1.x, b1.y, b1.z, b1.w};
#pragma unroll
            for (int i = 0; i < 8; i++) {
#pragma unroll
                for (int j = 0; j < 8; j++) {
                    acc[i][j] = fmaf(a[i], b[j], acc[i][j]);
                }
            }
        }

        if (kt + 1 < KT) {
            As[nxt][ac4 * 4 + 0][arow] = pa0.x;
            As[nxt][ac4 * 4 + 1][arow] = pa0.y;
            As[nxt][ac4 * 4 + 2][arow] = pa0.z;
            As[nxt][ac4 * 4 + 3][arow] = pa0.w;
            As[nxt][ac4 * 4 + 0][arow + 64] = pa1.x;
            As[nxt][ac4 * 4 + 1][arow + 64] = pa1.y;
            As[nxt][ac4 * 4 + 2][arow + 64] = pa1.z;
            As[nxt][ac4 * 4 + 3][arow + 64] = pa1.w;
            *(float4*)&Bs[nxt][br0][bc4 * 4] = pb0;
            *(float4*)&Bs[nxt][br0 + 8][bc4 * 4] = pb1;
        }
        __syncthreads();
    }

    float* yp = y + (long long)m0 * N + n0;
#pragma unroll
    for (int i = 0; i < 8; i++) {
        const int row = ty * 8 + i;
        float4 o0, o1;
        o0.x = acc[i][0]; o0.y = acc[i][1]; o0.z = acc[i][2]; o0.w = acc[i][3];
        o1.x = acc[i][4]; o1.y = acc[i][5]; o1.z = acc[i][6]; o1.w = acc[i][7];
        *(float4*)(yp + (long long)row * N + tx * 8) = o0;
        *(float4*)(yp + (long long)row * N + tx * 8 + 4) = o1;
    }
}

// ---------------------------------------------------------------------------
extern "C" void kernel_launch(void* const* d_in, const int* in_sizes, int n_in,
                              void* d_out, int out_size)
{
    const float* x  = (const float*)d_in[0];
    const float* wg = (const float*)d_in[1];
    const float* wu = (const float*)d_in[2];
    const float* wd = (const float*)d_in[3];
    float* y = (float*)d_out;

    const int grid1 = (M_DIM / 128) * (I_DIM / 64);    // 64 * 172 = 11008
    const int grid2 = (M_DIM / 128) * (H_DIM / 128);   // 64 * 32  = 2048

    k_gateup<<<grid1, 256>>>(x, wg, wu);
    k_down<<<grid2, 256>>>(wd, y);
}